// round 6
// baseline (speedup 1.0000x reference)
#include <cuda_runtime.h>
#include <cuda_fp16.h>
#include <cstdint>

// R6: fp16 mma.m16n8k16, 32x32 warp tiles, single-pass 128-col GEMMs,
// exact fp32 residual via global x re-reads. 2 CTAs/SM.

#define RSH  136   // halves stride for [64|128][128] fp16 buffers
#define RSV  72    // VbT [128][64] halves stride
#define SCS  72    // scores [64][64] halves stride
#define OSTS 132   // fp32 conv staging stride
#define TOK  64
#define CCH  128
#define VOLS 262144

__device__ __forceinline__ uint32_t pkhf(float lo, float hi) {
    uint32_t r; asm("cvt.rn.f16x2.f32 %0, %1, %2;" : "=r"(r) : "f"(hi), "f"(lo));
    return r;
}
__device__ __forceinline__ float2 uphf(uint32_t v) {
    __half2 h; *(uint32_t*)&h = v;
    return __half22float2(h);
}
__device__ __forceinline__ void mma16(float c[4], uint32_t a0, uint32_t a1,
                                      uint32_t a2, uint32_t a3,
                                      uint32_t b0, uint32_t b1) {
    asm volatile("mma.sync.aligned.m16n8k16.row.col.f32.f16.f16.f32 "
                 "{%0,%1,%2,%3}, {%4,%5,%6,%7}, {%8,%9}, {%0,%1,%2,%3};"
                 : "+f"(c[0]), "+f"(c[1]), "+f"(c[2]), "+f"(c[3])
                 : "r"(a0), "r"(a1), "r"(a2), "r"(a3), "r"(b0), "r"(b1));
}

// Warp computes rows [r0, r0+32) x cols [c0, c0+NT*8) of A(f16) * B(f16)^T.
// A: [rows][ras] k-contiguous halves; B: [cols][rbs] k-contiguous halves.
// C[i][j][0..1] = D[r0+16i+g][c0+8j+2t .. +1]; C[i][j][2..3] = row +8.
template<int KK, int NT>
__device__ __forceinline__ void mma_gemm2(const __half* __restrict__ A, int ras,
                                          const __half* __restrict__ B, int rbs,
                                          int r0, int c0, int g, int t,
                                          float C[2][NT][4]) {
#pragma unroll
    for (int i = 0; i < 2; i++)
#pragma unroll
        for (int j = 0; j < NT; j++)
#pragma unroll
            for (int q = 0; q < 4; q++) C[i][j][q] = 0.f;
    const __half* ap0 = A + (r0 + g) * ras + 2 * t;
    const __half* ap1 = ap0 + 8 * ras;
    const __half* ap2 = ap0 + 16 * ras;
    const __half* ap3 = ap0 + 24 * ras;
#pragma unroll
    for (int k0 = 0; k0 < KK; k0 += 16) {
        uint32_t a00 = *(const uint32_t*)(ap0 + k0);
        uint32_t a01 = *(const uint32_t*)(ap1 + k0);
        uint32_t a02 = *(const uint32_t*)(ap0 + k0 + 8);
        uint32_t a03 = *(const uint32_t*)(ap1 + k0 + 8);
        uint32_t a10 = *(const uint32_t*)(ap2 + k0);
        uint32_t a11 = *(const uint32_t*)(ap3 + k0);
        uint32_t a12 = *(const uint32_t*)(ap2 + k0 + 8);
        uint32_t a13 = *(const uint32_t*)(ap3 + k0 + 8);
#pragma unroll
        for (int j = 0; j < NT; j++) {
            const __half* bp = B + (c0 + j * 8 + g) * rbs + 2 * t;
            uint32_t b0 = *(const uint32_t*)(bp + k0);
            uint32_t b1 = *(const uint32_t*)(bp + k0 + 8);
            mma16(C[0][j], a00, a01, a02, a03, b0, b1);
            mma16(C[1][j], a10, a11, a12, a13, b0, b1);
        }
    }
}

__device__ __forceinline__ int voxoff(int tok) {
    return (tok >> 4) * 4096 + ((tok >> 2) & 3) * 64 + (tok & 3);
}

__global__ __launch_bounds__(256, 2)
void win_attn_kernel(const float* __restrict__ x,
                     const float* __restrict__ ln_g, const float* __restrict__ ln_b,
                     const float* __restrict__ Win,  const float* __restrict__ bin,
                     const float* __restrict__ Wout, const float* __restrict__ bout,
                     const float* __restrict__ Wc,   const float* __restrict__ bc,
                     float* __restrict__ out) {
    extern __shared__ char smbase[];
    __half* XN  = (__half*)smbase;       // [64][136]  x -> LN out -> attn o
    __half* Qb  = XN  + TOK * RSH;       // [64][136]  q -> y
    __half* WT  = Qb  + TOK * RSH;       // [128][136] weight tile
    __half* Kb  = WT  + CCH * RSH;       // [64][136]  k
    __half* VbT = Kb  + TOK * RSH;       // [128][72]  V transposed
    __half* SC  = VbT + CCH * RSV;       // [64][72]   scores/probs
    float*  OST = (float*)Kb;            // [64][132] fp32, overlaps Kb+VbT

    const int tid  = threadIdx.x;
    const int warp = tid >> 5;
    const int lane = tid & 31;
    const int g = lane >> 2, t = lane & 3;
    const int r0  = (warp & 1) * 32;        // big-GEMM warp m-base
    const int c0  = (warp >> 1) * 32;       // big-GEMM warp n-base (128 cols)
    const int c0s = (warp >> 1) * 16;       // scores n-base (64 cols)
    const int c0a = (warp >> 1) * 8;        // AV n-base (32 cols)

    const int wid = blockIdx.x;
    const int bb  = wid >> 12;
    const int rr  = wid & 4095;
    const int vd0 = (rr >> 8) * 4;
    const int vh0 = ((rr >> 4) & 15) * 4;
    const int vw0 = (rr & 15) * 4;
    const float* xb = x + (size_t)bb * ((size_t)CCH * VOLS);
    const size_t vox0 = (size_t)vd0 * 4096 + (size_t)vh0 * 64 + vw0;

    const int c0l = tid & 31, tq0 = tid >> 5;

    // ---- gather window into XN (fp16) ----
#pragma unroll
    for (int i = 0; i < 8; i++) {
        int c  = c0l + 32 * (i & 3);
        int tq = tq0 + 8 * (i >> 2);
        int dz = tq >> 2, dy = tq & 3;
        float4 v = *(const float4*)(xb + (size_t)c * VOLS + vox0 + dz * 4096 + dy * 64);
        __half* dst = XN + (tq * 4) * RSH + c;
        dst[0]       = __float2half(v.x);
        dst[RSH]     = __float2half(v.y);
        dst[2 * RSH] = __float2half(v.z);
        dst[3 * RSH] = __float2half(v.w);
    }
    __syncthreads();

    // ---- LayerNorm in place on XN (4 threads/token) ----
    {
        int tt = tid >> 2, sub = tid & 3;
        __half* row = XN + tt * RSH;
        float s = 0.f, ss = 0.f;
        float2 vals[16];
#pragma unroll
        for (int i = 0; i < 16; i++) {
            float2 v = uphf(*(const uint32_t*)(row + 2 * sub + 8 * i));
            vals[i] = v;
            s += v.x + v.y; ss += v.x * v.x + v.y * v.y;
        }
        s  += __shfl_xor_sync(0xffffffffu, s, 1);  s  += __shfl_xor_sync(0xffffffffu, s, 2);
        ss += __shfl_xor_sync(0xffffffffu, ss, 1); ss += __shfl_xor_sync(0xffffffffu, ss, 2);
        float mu = s * (1.f / 128.f);
        float var = ss * (1.f / 128.f) - mu * mu;
        float rstd = rsqrtf(var + 1e-5f);
#pragma unroll
        for (int i = 0; i < 16; i++) {
            int c = 2 * sub + 8 * i;
            float2 gl = *(const float2*)(ln_g + c);
            float2 bl = *(const float2*)(ln_b + c);
            *(uint32_t*)(row + c) = pkhf((vals[i].x - mu) * rstd * gl.x + bl.x,
                                         (vals[i].y - mu) * rstd * gl.y + bl.y);
        }
    }

    // ---- QKV: 3 single-pass GEMMs (128 out-cols each) ----
    for (int p = 0; p < 3; p++) {
        __syncthreads();
        for (int e = tid; e < 128 * 32; e += 256) {
            int o = e >> 5, k4 = e & 31;
            float4 w = *((const float4*)(Win + (size_t)(p * 128 + o) * 128) + k4);
            uint2 pk = { pkhf(w.x, w.y), pkhf(w.z, w.w) };
            *(uint2*)(WT + o * RSH + k4 * 4) = pk;
        }
        __syncthreads();
        float C[2][4][4];
        mma_gemm2<128, 4>(XN, RSH, WT, RSH, r0, c0, g, t, C);
        if (p < 2) {
            __half* dst = (p == 0) ? Qb : Kb;
#pragma unroll
            for (int i = 0; i < 2; i++) {
                int ra = r0 + 16 * i + g;
#pragma unroll
                for (int j = 0; j < 4; j++) {
                    int cl = c0 + 8 * j + 2 * t;
                    float2 b2 = *(const float2*)(bin + p * 128 + cl);
                    *(uint32_t*)(dst + ra * RSH + cl) =
                        pkhf(C[i][j][0] + b2.x, C[i][j][1] + b2.y);
                    *(uint32_t*)(dst + (ra + 8) * RSH + cl) =
                        pkhf(C[i][j][2] + b2.x, C[i][j][3] + b2.y);
                }
            }
        } else {
#pragma unroll
            for (int i = 0; i < 2; i++) {
                int ra = r0 + 16 * i + g;
#pragma unroll
                for (int j = 0; j < 4; j++) {
                    int cl = c0 + 8 * j + 2 * t;
                    float2 b2 = *(const float2*)(bin + 256 + cl);
                    VbT[(cl    ) * RSV + ra]     = __float2half(C[i][j][0] + b2.x);
                    VbT[(cl + 1) * RSV + ra]     = __float2half(C[i][j][1] + b2.y);
                    VbT[(cl    ) * RSV + ra + 8] = __float2half(C[i][j][2] + b2.x);
                    VbT[(cl + 1) * RSV + ra + 8] = __float2half(C[i][j][3] + b2.y);
                }
            }
        }
    }

    // ---- attention per head (hd=32) ----
    const float sc_norm = 0.17677669529663687f; // 1/sqrt(32)
    for (int hh = 0; hh < 4; hh++) {
        __syncthreads();
        {
            float Cs[2][2][4];
            mma_gemm2<32, 2>(Qb + hh * 32, RSH, Kb + hh * 32, RSH, r0, c0s, g, t, Cs);
#pragma unroll
            for (int i = 0; i < 2; i++) {
                int ra = r0 + 16 * i + g;
#pragma unroll
                for (int j = 0; j < 2; j++) {
                    int cl = c0s + 8 * j + 2 * t;
                    *(uint32_t*)(SC + ra * SCS + cl) =
                        pkhf(Cs[i][j][0] * sc_norm, Cs[i][j][1] * sc_norm);
                    *(uint32_t*)(SC + (ra + 8) * SCS + cl) =
                        pkhf(Cs[i][j][2] * sc_norm, Cs[i][j][3] * sc_norm);
                }
            }
        }
        __syncthreads();
        // softmax (4 threads/row)
        {
            int rrow = tid >> 2, sub = tid & 3;
            __half* row = SC + rrow * SCS + 2 * sub;
            float2 v[8];
            float m = -1e30f;
#pragma unroll
            for (int i = 0; i < 8; i++) {
                v[i] = uphf(*(const uint32_t*)(row + 8 * i));
                m = fmaxf(m, fmaxf(v[i].x, v[i].y));
            }
            m = fmaxf(m, __shfl_xor_sync(0xffffffffu, m, 1));
            m = fmaxf(m, __shfl_xor_sync(0xffffffffu, m, 2));
            float s = 0.f;
#pragma unroll
            for (int i = 0; i < 8; i++) {
                v[i].x = __expf(v[i].x - m);
                v[i].y = __expf(v[i].y - m);
                s += v[i].x + v[i].y;
            }
            s += __shfl_xor_sync(0xffffffffu, s, 1);
            s += __shfl_xor_sync(0xffffffffu, s, 2);
            float inv = 1.f / s;
#pragma unroll
            for (int i = 0; i < 8; i++)
                *(uint32_t*)(row + 8 * i) = pkhf(v[i].x * inv, v[i].y * inv);
        }
        __syncthreads();
        // o_h = P @ V_h : warp tile 32x8
        {
            float Ca[2][1][4];
            mma_gemm2<64, 1>(SC, SCS, VbT + (hh * 32) * RSV, RSV, r0, c0a, g, t, Ca);
#pragma unroll
            for (int i = 0; i < 2; i++) {
                int ra = r0 + 16 * i + g;
                int cl = hh * 32 + c0a + 2 * t;
                *(uint32_t*)(XN + ra * RSH + cl)       = pkhf(Ca[i][0][0], Ca[i][0][1]);
                *(uint32_t*)(XN + (ra + 8) * RSH + cl) = pkhf(Ca[i][0][2], Ca[i][0][3]);
            }
        }
    }

    // ---- out_proj: y = x_exact + o @ Wout^T + bout -> Qb (fp16) ----
    __syncthreads();
    for (int e = tid; e < 128 * 32; e += 256) {
        int o = e >> 5, k4 = e & 31;
        float4 w = *((const float4*)(Wout + (size_t)o * 128) + k4);
        uint2 pk = { pkhf(w.x, w.y), pkhf(w.z, w.w) };
        *(uint2*)(WT + o * RSH + k4 * 4) = pk;
    }
    __syncthreads();
    {
        float C[2][4][4];
        mma_gemm2<128, 4>(XN, RSH, WT, RSH, r0, c0, g, t, C);
#pragma unroll
        for (int i = 0; i < 2; i++) {
            int ra = r0 + 16 * i + g;
            int rb = ra + 8;
            size_t va = vox0 + voxoff(ra);
            size_t vb = vox0 + voxoff(rb);
#pragma unroll
            for (int j = 0; j < 4; j++) {
                int cl = c0 + 8 * j + 2 * t;
                float2 b2 = *(const float2*)(bout + cl);
                const float* x0 = xb + (size_t)cl * VOLS;
                const float* x1 = x0 + VOLS;
                *(uint32_t*)(Qb + ra * RSH + cl) =
                    pkhf(C[i][j][0] + b2.x + x0[va], C[i][j][1] + b2.y + x1[va]);
                *(uint32_t*)(Qb + rb * RSH + cl) =
                    pkhf(C[i][j][2] + b2.x + x0[vb], C[i][j][3] + b2.y + x1[vb]);
            }
        }
    }

    // ---- 1x1x1 conv: C -> OST (fp32, overlaps Kb/VbT) ----
    __syncthreads();
    for (int e = tid; e < 128 * 32; e += 256) {
        int o = e >> 5, k4 = e & 31;
        float4 w = *((const float4*)(Wc + (size_t)o * 128) + k4);
        uint2 pk = { pkhf(w.x, w.y), pkhf(w.z, w.w) };
        *(uint2*)(WT + o * RSH + k4 * 4) = pk;
    }
    __syncthreads();
    {
        float C[2][4][4];
        mma_gemm2<128, 4>(Qb, RSH, WT, RSH, r0, c0, g, t, C);
#pragma unroll
        for (int i = 0; i < 2; i++) {
            int ra = r0 + 16 * i + g;
#pragma unroll
            for (int j = 0; j < 4; j++) {
                int cl = c0 + 8 * j + 2 * t;
                float2 b2 = *(const float2*)(bc + cl);
                float2 v0 = { C[i][j][0] + b2.x, C[i][j][1] + b2.y };
                float2 v1 = { C[i][j][2] + b2.x, C[i][j][3] + b2.y };
                *(float2*)(OST + ra * OSTS + cl)       = v0;
                *(float2*)(OST + (ra + 8) * OSTS + cl) = v1;
            }
        }
    }
    __syncthreads();

    // ---- epilogue: out = OST + x (exact fp32 residual), coalesced ----
    float* outp = out + (size_t)bb * ((size_t)CCH * VOLS);
#pragma unroll
    for (int i = 0; i < 8; i++) {
        int c  = c0l + 32 * (i & 3);
        int tq = tq0 + 8 * (i >> 2);
        int dz = tq >> 2, dy = tq & 3;
        size_t gaddr = (size_t)c * VOLS + vox0 + dz * 4096 + dy * 64;
        float4 xv = *(const float4*)(xb + gaddr);
        const float* src = OST + (tq * 4) * OSTS + c;
        float4 v = { src[0] + xv.x, src[OSTS] + xv.y,
                     src[2 * OSTS] + xv.z, src[3 * OSTS] + xv.w };
        *(float4*)(outp + gaddr) = v;
    }
}

// halves: XN 8704 + Qb 8704 + WT 17408 + Kb 8704 + VbT 9216 + SC 4608 = 57344
static const int SMEM_BYTES = 57344 * 2; // 114688 B

extern "C" void kernel_launch(void* const* d_in, const int* in_sizes, int n_in,
                              void* d_out, int out_size) {
    const float* x    = (const float*)d_in[0];
    const float* ln_g = (const float*)d_in[1];
    const float* ln_b = (const float*)d_in[2];
    const float* Win  = (const float*)d_in[3];
    const float* bin  = (const float*)d_in[4];
    const float* Wout = (const float*)d_in[5];
    const float* bout = (const float*)d_in[6];
    const float* Wc   = (const float*)d_in[7];
    const float* bc   = (const float*)d_in[8];
    float* out = (float*)d_out;

    cudaFuncSetAttribute(win_attn_kernel,
                         cudaFuncAttributeMaxDynamicSharedMemorySize, SMEM_BYTES);
    win_attn_kernel<<<8192, 256, SMEM_BYTES>>>(x, ln_g, ln_b, Win, bin,
                                               Wout, bout, Wc, bc, out);
}